// round 6
// baseline (speedup 1.0000x reference)
#include <cuda_runtime.h>
#include <cuda_fp16.h>
#include <cuda_bf16.h>
#include <cstdint>
#include <math.h>

// ConvergedInhibition == circular deconvolution along C=128 channels.
// Y = G @ X, G[r][j] = g[(r-j)&127], g = ifft(1/fft(delta-k)).
// R6: R5 (2-pass fp16 split, 64mx32n warp tiles) + column-permuted B layout
//     so each lane's accumulators are 8 CONSECUTIVE output columns ->
//     fully-coalesced STG.128 epilogue (halves STG L1 wavefronts).

#define CCH     128
#define HWSZ    4096
#define NBATCH  64
#define SCOPE   27
#define NTILE   128
#define NTHREADS 256

#define XPITCH_B 272                       // bytes per n-row (17*16B)
#define SMEM_XH  0
#define SMEM_XL  (NTILE * XPITCH_B)        // 34816
#define SMEM_DYN (2 * NTILE * XPITCH_B)    // 69632

__device__ float g_vec[CCH];
__device__ uint4 a_frag[8 * 8 * 32];       // [mtile][kstep][lane], fp16 G, 32KB

// ---------------------------------------------------------------------------
__device__ __forceinline__ uint32_t s2u(const void* p) {
    uint32_t a;
    asm("{ .reg .u64 t; cvta.to.shared.u64 t, %1; cvt.u32.u64 %0, t; }"
        : "=r"(a) : "l"(p));
    return a;
}
__device__ __forceinline__ uint32_t pack_f16x2(float lo, float hi) {
    uint32_t r;
    asm("cvt.rn.f16x2.f32 %0, %1, %2;" : "=r"(r) : "f"(hi), "f"(lo));
    return r;
}
__device__ __forceinline__ void ldsm_x4(uint32_t& r0, uint32_t& r1,
                                        uint32_t& r2, uint32_t& r3, uint32_t a) {
    asm volatile("ldmatrix.sync.aligned.m8n8.x4.shared.b16 {%0,%1,%2,%3}, [%4];"
                 : "=r"(r0), "=r"(r1), "=r"(r2), "=r"(r3) : "r"(a));
}
__device__ __forceinline__ void mma16816(float* c, const uint4& a,
                                         uint32_t b0, uint32_t b1) {
    asm volatile(
        "mma.sync.aligned.m16n8k16.row.col.f32.f16.f16.f32 "
        "{%0,%1,%2,%3}, {%4,%5,%6,%7}, {%8,%9}, {%0,%1,%2,%3};"
        : "+f"(c[0]), "+f"(c[1]), "+f"(c[2]), "+f"(c[3])
        : "r"(a.x), "r"(a.y), "r"(a.z), "r"(a.w), "r"(b0), "r"(b1));
}

// ---------------------------------------------------------------------------
// Prep: compute g (validated R1), write fp16 mma A-fragment table.
// ---------------------------------------------------------------------------
__global__ void prep_kernel(const float* __restrict__ filt) {
    __shared__ float tw_re[CCH], tw_im[CCH];
    __shared__ float inv_re[CCH], inv_im[CCH];
    __shared__ float ft[SCOPE];
    __shared__ float g_s[CCH];
    int t = threadIdx.x;   // 0..255
    if (t < SCOPE) ft[t] = filt[t];
    if (t < CCH) {
        float s, c;
        sincosf(6.283185307179586f * (float)t / 128.0f, &s, &c);
        tw_re[t] = c; tw_im[t] = s;
    }
    __syncthreads();
    if (t < CCH) {
        float fr = 1.0f, fi = 0.0f;
#pragma unroll
        for (int j = 0; j < SCOPE; j++) {
            int p = (115 + j) & 127;
            int idx = (t * p) & 127;
            fr -= ft[j] * tw_re[idx];
            fi += ft[j] * tw_im[idx];
        }
        float d = fr * fr + fi * fi;
        inv_re[t] = fr / d; inv_im[t] = -fi / d;
    }
    __syncthreads();
    if (t < CCH) {
        float acc = 0.0f;
        for (int f = 0; f < CCH; f++) {
            int idx = (f * t) & 127;
            acc += tw_re[idx] * inv_re[f] - tw_im[idx] * inv_im[f];
        }
        float g = acc * (1.0f / 128.0f);
        g_vec[t] = g;
        g_s[t] = g;
    }
    __syncthreads();

    for (int e = t; e < 8 * 8 * 32; e += 256) {
        int lane = e & 31;
        int ks   = (e >> 5) & 7;
        int mt   = e >> 8;
        int m = mt * 16 + (lane >> 2);
        int k = ks * 16 + 2 * (lane & 3);
        uint4 h;
        int d0 = (m - k) & 127;
        h.x = pack_f16x2(g_s[d0], g_s[(d0 - 1) & 127]);
        int d1 = (m + 8 - k) & 127;
        h.y = pack_f16x2(g_s[d1], g_s[(d1 - 1) & 127]);
        int d2 = (m - k - 8) & 127;
        h.z = pack_f16x2(g_s[d2], g_s[(d2 - 1) & 127]);
        h.w = h.x;   // (m+8)-(k+8) == m-k
        a_frag[e] = h;
    }
}

// ---------------------------------------------------------------------------
// GEMM: one CTA = 128 out-channels x 128 spatial cols, K=128.
// Column permutation (within each 32-col block): global col
//   nu = 8q + 2nt + b  is stored at smem row  n = 8nt + 2q + b
// (involution: apply the same bit-field swap both ways). The mma fragment
// position n = 8nt + 2(lane&3) + b then holds global col 8(lane&3)+2nt+b,
// so each lane accumulates 8 consecutive output columns.
// ---------------------------------------------------------------------------
__global__ void __launch_bounds__(NTHREADS, 2)
gemm_mma(const float* __restrict__ x, float* __restrict__ y) {
    extern __shared__ char smc[];
    const int tid  = threadIdx.x;
    const int wid  = tid >> 5;
    const int lane = tid & 31;
    const int warp_m = wid & 1;
    const int warp_n = wid >> 1;

    const int b     = blockIdx.x;
    const int batch = b >> 5;
    const int col0  = (b & 31) * NTILE;
    const float* xb = x + (size_t)batch * CCH * HWSZ + col0;
    float*       yb = y + (size_t)batch * CCH * HWSZ + col0;

    // ---- Load X tile (permuted cols), fp16 hi/lo split, STS.128 ----
    {
        const int n0 = tid & 127;                    // smem row
        const int rr = n0 & 31;
        const int nu = ((rr & 6) << 2) | ((rr >> 2) & 6) | (rr & 1);
        char* dst_h = smc + SMEM_XH + (uint32_t)n0 * XPITCH_B;
        char* dst_l = smc + SMEM_XL + (uint32_t)n0 * XPITCH_B;
        const float* pbase = xb + (n0 & ~31) + nu;   // permuted global col
#pragma unroll
        for (int j = 0; j < 8; j++) {
            int oct = (tid >> 7) + 2 * j;            // 0..15
            const float* p = pbase + (size_t)(oct * 8) * HWSZ;
            float v[8];
#pragma unroll
            for (int i = 0; i < 8; i++) v[i] = __ldg(p + (size_t)i * HWSZ);
            uint4 hq;
            hq.x = pack_f16x2(v[0], v[1]);
            hq.y = pack_f16x2(v[2], v[3]);
            hq.z = pack_f16x2(v[4], v[5]);
            hq.w = pack_f16x2(v[6], v[7]);
            float l[8];
            {
                __half2 t0 = *reinterpret_cast<__half2*>(&hq.x);
                __half2 t1 = *reinterpret_cast<__half2*>(&hq.y);
                __half2 t2 = *reinterpret_cast<__half2*>(&hq.z);
                __half2 t3 = *reinterpret_cast<__half2*>(&hq.w);
                float2 f0 = __half22float2(t0);
                float2 f1 = __half22float2(t1);
                float2 f2 = __half22float2(t2);
                float2 f3 = __half22float2(t3);
                l[0] = v[0] - f0.x; l[1] = v[1] - f0.y;
                l[2] = v[2] - f1.x; l[3] = v[3] - f1.y;
                l[4] = v[4] - f2.x; l[5] = v[5] - f2.y;
                l[6] = v[6] - f3.x; l[7] = v[7] - f3.y;
            }
            uint4 lq;
            lq.x = pack_f16x2(l[0], l[1]);
            lq.y = pack_f16x2(l[2], l[3]);
            lq.z = pack_f16x2(l[4], l[5]);
            lq.w = pack_f16x2(l[6], l[7]);
            *reinterpret_cast<uint4*>(dst_h + oct * 16) = hq;
            *reinterpret_cast<uint4*>(dst_l + oct * 16) = lq;
        }
    }
    __syncthreads();

    // ---- MMA mainloop: 4 mtiles x 4 ntiles, 2 passes (Xh, Xl) ----
    float acc[4][4][4];
#pragma unroll
    for (int mt = 0; mt < 4; mt++)
#pragma unroll
        for (int nt = 0; nt < 4; nt++)
#pragma unroll
            for (int r = 0; r < 4; r++) acc[mt][nt][r] = 0.0f;

    const uint32_t lm_off = ((lane & 7) + ((lane >> 4) << 3)) * XPITCH_B
                          + ((lane >> 3) & 1) * 16;
    const uint32_t xh_base = s2u(smc) + SMEM_XH
                           + (uint32_t)warp_n * 32 * XPITCH_B + lm_off;
    const uint32_t xl_base = xh_base + SMEM_XL;
    const int fbase = (warp_m * 4) * 8 * 32 + lane;   // first of 4 mtiles

#pragma unroll
    for (int ks = 0; ks < 8; ks++) {
        uint4 a0 = a_frag[fbase + (0 * 8 + ks) * 32];
        uint4 a1 = a_frag[fbase + (1 * 8 + ks) * 32];
        uint4 a2 = a_frag[fbase + (2 * 8 + ks) * 32];
        uint4 a3 = a_frag[fbase + (3 * 8 + ks) * 32];
        uint32_t kofs = ks * 32;
#pragma unroll
        for (int p = 0; p < 2; p++) {
            uint32_t bh0, bh1, bh2, bh3, bl0, bl1, bl2, bl3;
            ldsm_x4(bh0, bh1, bh2, bh3, xh_base + p * (16 * XPITCH_B) + kofs);
            ldsm_x4(bl0, bl1, bl2, bl3, xl_base + p * (16 * XPITCH_B) + kofs);
            mma16816(acc[0][2 * p],     a0, bh0, bh1);
            mma16816(acc[1][2 * p],     a1, bh0, bh1);
            mma16816(acc[2][2 * p],     a2, bh0, bh1);
            mma16816(acc[3][2 * p],     a3, bh0, bh1);
            mma16816(acc[0][2 * p + 1], a0, bh2, bh3);
            mma16816(acc[1][2 * p + 1], a1, bh2, bh3);
            mma16816(acc[2][2 * p + 1], a2, bh2, bh3);
            mma16816(acc[3][2 * p + 1], a3, bh2, bh3);
            mma16816(acc[0][2 * p],     a0, bl0, bl1);
            mma16816(acc[1][2 * p],     a1, bl0, bl1);
            mma16816(acc[2][2 * p],     a2, bl0, bl1);
            mma16816(acc[3][2 * p],     a3, bl0, bl1);
            mma16816(acc[0][2 * p + 1], a0, bl2, bl3);
            mma16816(acc[1][2 * p + 1], a1, bl2, bl3);
            mma16816(acc[2][2 * p + 1], a2, bl2, bl3);
            mma16816(acc[3][2 * p + 1], a3, bl2, bl3);
        }
    }

    // ---- Epilogue: lane holds cols [8q, 8q+8) of rows m0, m0+8 per mtile ----
    {
        const int q = lane & 3;
#pragma unroll
        for (int mt = 0; mt < 4; mt++) {
            int m0 = warp_m * 64 + mt * 16 + (lane >> 2);
            float* yr0 = yb + (size_t)m0 * HWSZ + warp_n * 32 + 8 * q;
            float* yr8 = yr0 + (size_t)8 * HWSZ;
            // nt=0 -> cols 8q+0,1 ; nt=1 -> +2,3 ; nt=2 -> +4,5 ; nt=3 -> +6,7
            *reinterpret_cast<float4*>(yr0) =
                make_float4(acc[mt][0][0], acc[mt][0][1],
                            acc[mt][1][0], acc[mt][1][1]);
            *reinterpret_cast<float4*>(yr0 + 4) =
                make_float4(acc[mt][2][0], acc[mt][2][1],
                            acc[mt][3][0], acc[mt][3][1]);
            *reinterpret_cast<float4*>(yr8) =
                make_float4(acc[mt][0][2], acc[mt][0][3],
                            acc[mt][1][2], acc[mt][1][3]);
            *reinterpret_cast<float4*>(yr8 + 4) =
                make_float4(acc[mt][2][2], acc[mt][2][3],
                            acc[mt][3][2], acc[mt][3][3]);
        }
    }
}

// ---------------------------------------------------------------------------
extern "C" void kernel_launch(void* const* d_in, const int* in_sizes, int n_in,
                              void* d_out, int out_size) {
    const float* act  = (const float*)d_in[0];
    const float* filt = (const float*)d_in[1];
    if (n_in >= 2 && in_sizes[0] == SCOPE) {
        act  = (const float*)d_in[1];
        filt = (const float*)d_in[0];
    }
    float* out = (float*)d_out;

    prep_kernel<<<1, 256>>>(filt);

    cudaFuncSetAttribute(gemm_mma,
                         cudaFuncAttributeMaxDynamicSharedMemorySize, SMEM_DYN);
    gemm_mma<<<NBATCH * (HWSZ / NTILE), NTHREADS, SMEM_DYN>>>(act, out);
}

// round 7
// speedup vs baseline: 1.0965x; 1.0965x over previous
#include <cuda_runtime.h>
#include <cuda_fp16.h>
#include <cstdint>
#include <math.h>

// ConvergedInhibition == circular deconvolution along C=128 channels.
// Y = G @ X, G[r][j] = g[(r-j)&127], g = ifft(1/fft(delta-k)).
// R7: single-pass fp16 mma (G16 @ X16, rel_err ~3e-4 by calibrated model),
//     A-fragments held in registers via circulant diagonal classes
//     ((mt - ks) mod 8 -> only 8 distinct uint4 frags per lane),
//     permuted-column coalesced STG.128 epilogue (R6).

#define CCH     128
#define HWSZ    4096
#define NBATCH  64
#define SCOPE   27
#define NTILE   128
#define NTHREADS 256

#define XPITCH_B 272                       // bytes per n-row (17*16B)
#define SMEM_DYN (NTILE * XPITCH_B)        // 34816

__device__ uint4 a_frag8[8 * 32];          // [class][lane], fp16 G frags, 4KB

// ---------------------------------------------------------------------------
__device__ __forceinline__ uint32_t s2u(const void* p) {
    uint32_t a;
    asm("{ .reg .u64 t; cvta.to.shared.u64 t, %1; cvt.u32.u64 %0, t; }"
        : "=r"(a) : "l"(p));
    return a;
}
__device__ __forceinline__ uint32_t pack_f16x2(float lo, float hi) {
    uint32_t r;
    asm("cvt.rn.f16x2.f32 %0, %1, %2;" : "=r"(r) : "f"(hi), "f"(lo));
    return r;
}
__device__ __forceinline__ void ldsm_x4(uint32_t& r0, uint32_t& r1,
                                        uint32_t& r2, uint32_t& r3, uint32_t a) {
    asm volatile("ldmatrix.sync.aligned.m8n8.x4.shared.b16 {%0,%1,%2,%3}, [%4];"
                 : "=r"(r0), "=r"(r1), "=r"(r2), "=r"(r3) : "r"(a));
}
__device__ __forceinline__ void mma16816(float* c, const uint4& a,
                                         uint32_t b0, uint32_t b1) {
    asm volatile(
        "mma.sync.aligned.m16n8k16.row.col.f32.f16.f16.f32 "
        "{%0,%1,%2,%3}, {%4,%5,%6,%7}, {%8,%9}, {%0,%1,%2,%3};"
        : "+f"(c[0]), "+f"(c[1]), "+f"(c[2]), "+f"(c[3])
        : "r"(a.x), "r"(a.y), "r"(a.z), "r"(a.w), "r"(b0), "r"(b1));
}

// ---------------------------------------------------------------------------
// Prep: compute g (validated R1), write the 8-class A-fragment table.
// Class c covers all (mt, ks) with (warp_m*4 + mt - ks) mod 8 == c:
//   d0 = (16c + (lane>>2) - 2(lane&3)) & 127
//   h.x = f16x2(g[d0], g[d0-1]); h.y: d0+8; h.z: d0-8; h.w = h.x
// ---------------------------------------------------------------------------
__global__ void prep_kernel(const float* __restrict__ filt) {
    __shared__ float tw_re[CCH], tw_im[CCH];
    __shared__ float inv_re[CCH], inv_im[CCH];
    __shared__ float ft[SCOPE];
    __shared__ float g_s[CCH];
    int t = threadIdx.x;   // 0..255
    if (t < SCOPE) ft[t] = filt[t];
    if (t < CCH) {
        float s, c;
        sincosf(6.283185307179586f * (float)t / 128.0f, &s, &c);
        tw_re[t] = c; tw_im[t] = s;
    }
    __syncthreads();
    if (t < CCH) {
        float fr = 1.0f, fi = 0.0f;
#pragma unroll
        for (int j = 0; j < SCOPE; j++) {
            int p = (115 + j) & 127;
            int idx = (t * p) & 127;
            fr -= ft[j] * tw_re[idx];
            fi += ft[j] * tw_im[idx];
        }
        float d = fr * fr + fi * fi;
        inv_re[t] = fr / d; inv_im[t] = -fi / d;
    }
    __syncthreads();
    if (t < CCH) {
        float acc = 0.0f;
        for (int f = 0; f < CCH; f++) {
            int idx = (f * t) & 127;
            acc += tw_re[idx] * inv_re[f] - tw_im[idx] * inv_im[f];
        }
        g_s[t] = acc * (1.0f / 128.0f);
    }
    __syncthreads();

    {
        int cls  = t >> 5;          // 0..7
        int lane = t & 31;
        int d0 = (16 * cls + (lane >> 2) - 2 * (lane & 3)) & 127;
        uint4 h;
        h.x = pack_f16x2(g_s[d0], g_s[(d0 - 1) & 127]);
        int d1 = (d0 + 8) & 127;
        h.y = pack_f16x2(g_s[d1], g_s[(d1 - 1) & 127]);
        int d2 = (d0 - 8) & 127;
        h.z = pack_f16x2(g_s[d2], g_s[(d2 - 1) & 127]);
        h.w = h.x;
        a_frag8[t] = h;
    }
}

// ---------------------------------------------------------------------------
// GEMM: one CTA = 128 out-channels x 128 spatial cols, K=128.
// 8 warps: warp_m = wid&1 (64 rows), warp_n = wid>>1 (32 cols).
// Column permutation within 32-col blocks (R6): global col nu = 8q+2nt+b
// stored at smem row n = 8nt+2q+b -> lane accumulates 8 consecutive cols.
// ---------------------------------------------------------------------------
__global__ void __launch_bounds__(NTHREADS, 2)
gemm_mma(const float* __restrict__ x, float* __restrict__ y) {
    extern __shared__ char smc[];
    const int tid  = threadIdx.x;
    const int wid  = tid >> 5;
    const int lane = tid & 31;
    const int warp_m = wid & 1;
    const int warp_n = wid >> 1;

    const int b     = blockIdx.x;
    const int batch = b >> 5;
    const int col0  = (b & 31) * NTILE;
    const float* xb = x + (size_t)batch * CCH * HWSZ + col0;
    float*       yb = y + (size_t)batch * CCH * HWSZ + col0;

    // ---- A fragments for the whole mainloop: 8 diagonal classes in regs.
    // areg[i] = table[(warp_m*4 + i) & 7] so mainloop index (mt-ks)&7 is static.
    uint4 areg[8];
#pragma unroll
    for (int i = 0; i < 8; i++)
        areg[i] = a_frag8[(((warp_m << 2) + i) & 7) * 32 + lane];

    // ---- Load X tile (permuted cols), fp16 convert, conflict-free STS.128 ----
    {
        const int n0 = tid & 127;                    // smem row
        const int rr = n0 & 31;
        const int nu = ((rr & 6) << 2) | ((rr >> 2) & 6) | (rr & 1);
        char* dst = smc + (uint32_t)n0 * XPITCH_B;
        const float* pbase = xb + (n0 & ~31) + nu;   // permuted global col
#pragma unroll
        for (int j = 0; j < 8; j++) {
            int oct = (tid >> 7) + 2 * j;            // 0..15
            const float* p = pbase + (size_t)(oct * 8) * HWSZ;
            float v[8];
#pragma unroll
            for (int i = 0; i < 8; i++) v[i] = __ldg(p + (size_t)i * HWSZ);
            uint4 hq;
            hq.x = pack_f16x2(v[0], v[1]);
            hq.y = pack_f16x2(v[2], v[3]);
            hq.z = pack_f16x2(v[4], v[5]);
            hq.w = pack_f16x2(v[6], v[7]);
            *reinterpret_cast<uint4*>(dst + oct * 16) = hq;
        }
    }
    __syncthreads();

    // ---- MMA mainloop: 4 mtiles x 4 ntiles, single fp16 pass ----
    float acc[4][4][4];
#pragma unroll
    for (int mt = 0; mt < 4; mt++)
#pragma unroll
        for (int nt = 0; nt < 4; nt++)
#pragma unroll
            for (int r = 0; r < 4; r++) acc[mt][nt][r] = 0.0f;

    const uint32_t lm_off = ((lane & 7) + ((lane >> 4) << 3)) * XPITCH_B
                          + ((lane >> 3) & 1) * 16;
    const uint32_t xh_base = s2u(smc) + (uint32_t)warp_n * 32 * XPITCH_B + lm_off;

#pragma unroll
    for (int ks = 0; ks < 8; ks++) {
        uint32_t kofs = ks * 32;
#pragma unroll
        for (int p = 0; p < 2; p++) {
            uint32_t b0, b1, b2, b3;
            ldsm_x4(b0, b1, b2, b3, xh_base + p * (16 * XPITCH_B) + kofs);
#pragma unroll
            for (int mt = 0; mt < 4; mt++) {
                const uint4& a = areg[(mt - ks) & 7];   // static index
                mma16816(acc[mt][2 * p],     a, b0, b1);
                mma16816(acc[mt][2 * p + 1], a, b2, b3);
            }
        }
    }

    // ---- Epilogue: lane holds cols [8q, 8q+8) of rows m0, m0+8 per mtile ----
    {
        const int q = lane & 3;
#pragma unroll
        for (int mt = 0; mt < 4; mt++) {
            int m0 = warp_m * 64 + mt * 16 + (lane >> 2);
            float* yr0 = yb + (size_t)m0 * HWSZ + warp_n * 32 + 8 * q;
            float* yr8 = yr0 + (size_t)8 * HWSZ;
            *reinterpret_cast<float4*>(yr0) =
                make_float4(acc[mt][0][0], acc[mt][0][1],
                            acc[mt][1][0], acc[mt][1][1]);
            *reinterpret_cast<float4*>(yr0 + 4) =
                make_float4(acc[mt][2][0], acc[mt][2][1],
                            acc[mt][3][0], acc[mt][3][1]);
            *reinterpret_cast<float4*>(yr8) =
                make_float4(acc[mt][0][2], acc[mt][0][3],
                            acc[mt][1][2], acc[mt][1][3]);
            *reinterpret_cast<float4*>(yr8 + 4) =
                make_float4(acc[mt][2][2], acc[mt][2][3],
                            acc[mt][3][2], acc[mt][3][3]);
        }
    }
}

// ---------------------------------------------------------------------------
extern "C" void kernel_launch(void* const* d_in, const int* in_sizes, int n_in,
                              void* d_out, int out_size) {
    const float* act  = (const float*)d_in[0];
    const float* filt = (const float*)d_in[1];
    if (n_in >= 2 && in_sizes[0] == SCOPE) {
        act  = (const float*)d_in[1];
        filt = (const float*)d_in[0];
    }
    float* out = (float*)d_out;

    prep_kernel<<<1, 256>>>(filt);

    cudaFuncSetAttribute(gemm_mma,
                         cudaFuncAttributeMaxDynamicSharedMemorySize, SMEM_DYN);
    gemm_mma<<<NBATCH * (HWSZ / NTILE), NTHREADS, SMEM_DYN>>>(act, out);
}